// round 8
// baseline (speedup 1.0000x reference)
#include <cuda_runtime.h>
#include <cstdint>

// ---------------------------------------------------------------------------
// out = concat( relu(A@relu(A@F)), A@(A@NF) ), N=8192, D=E=64.
// Both layers: C[8192,128] = A[8192,8192] @ W[8192,128], relu on cols<64.
// Path: int8 IMMA (mma.m16n8k32.u8.s8) two-digit fixed point.
//   A (nonneg, < 2^-13):  a = 2^-21*q1 + 2^-29*q2   (u8 digits, exact ratios)
//   B:                    b = sB*(p1 + p2/256)      (s8 digits, sB = maxB/127)
//   C = 2^-21*sB * ( Q1P1 + (Q1P2 + Q2P1)/256 )     (int32 accum, exact)
// ---------------------------------------------------------------------------

constexpr int NN  = 8192;
constexpr int WID = 128;

// smem: int8 tiles, rows of 32 bytes at pitch 48 (conflict-free ldmatrix)
constexpr int PITCH   = 48;
constexpr int AQ1_OFF = 0;                    // 64 rows -> 3072 B
constexpr int AQ2_OFF = 3072;
constexpr int BP1_OFF = 6144;                 // 128 rows -> 6144 B
constexpr int BP2_OFF = 12288;
constexpr int BUF_BYTES = 18432;
constexpr int SMEM_GEMM = 2 * BUF_BYTES;      // 36864 (>= 34816 epilogue)

// B digit operands, stored [n][k] (k contiguous) == col-major B for mma.
__device__ __align__(16) int8_t g_P1b1[(size_t)WID * NN];
__device__ __align__(16) int8_t g_P2b1[(size_t)WID * NN];
__device__ __align__(16) int8_t g_P1b2[(size_t)WID * NN];
__device__ __align__(16) int8_t g_P2b2[(size_t)WID * NN];
__device__ __align__(16) float  g_C1[(size_t)WID * NN];   // layer-1 out, [n][k]
__device__ unsigned g_maxW = 0;   // max|W|  bits (set once; idempotent replays)
__device__ unsigned g_maxC = 0;   // max|C1| bits

// ---------------------------------------------------------------------------
// helpers
// ---------------------------------------------------------------------------
__device__ __forceinline__ uint32_t s2u(const void* p) {
    uint32_t a;
    asm("{ .reg .u64 t; cvta.to.shared.u64 t, %1; cvt.u32.u64 %0, t; }"
        : "=r"(a) : "l"(p));
    return a;
}

__device__ __forceinline__ void ldmx4(uint32_t* r, uint32_t addr) {
    asm volatile("ldmatrix.sync.aligned.m8n8.x4.shared.b16 {%0,%1,%2,%3}, [%4];"
                 : "=r"(r[0]), "=r"(r[1]), "=r"(r[2]), "=r"(r[3]) : "r"(addr));
}

__device__ __forceinline__ void imma(int* c, const uint32_t* a, const uint32_t* b) {
    asm volatile(
        "mma.sync.aligned.m16n8k32.row.col.s32.u8.s8.s32 "
        "{%0,%1,%2,%3}, {%4,%5,%6,%7}, {%8,%9}, {%0,%1,%2,%3};"
        : "+r"(c[0]), "+r"(c[1]), "+r"(c[2]), "+r"(c[3])
        : "r"(a[0]), "r"(a[1]), "r"(a[2]), "r"(a[3]), "r"(b[0]), "r"(b[1]));
}

// quantize 8 fp32 A elems (in [0,2^-13)) -> 8 u8 hi digits + 8 u8 lo digits
__device__ __forceinline__ void quantA8(float4 x, float4 y, uint2& d1, uint2& d2) {
    float v[8] = {x.x, x.y, x.z, x.w, y.x, y.y, y.z, y.w};
    uint32_t w1[2] = {0u, 0u}, w2[2] = {0u, 0u};
    #pragma unroll
    for (int i = 0; i < 8; ++i) {
        float f = v[i] * 2097152.0f;            // * 2^21  -> [0,256)
        uint32_t q1 = (uint32_t)f;              // floor
        float fr = f - (float)q1;               // exact, [0,1)
        uint32_t q2 = (uint32_t)(fr * 256.0f);  // floor, [0,255]
        w1[i >> 2] |= q1 << ((i & 3) * 8);
        w2[i >> 2] |= q2 << ((i & 3) * 8);
    }
    d1 = make_uint2(w1[0], w1[1]);
    d2 = make_uint2(w2[0], w2[1]);
}

// quantize one fp32 b -> s8 digit pair, given s1 = M/127
__device__ __forceinline__ void quantB(float v, float s1, float inv1,
                                       int8_t& p1, int8_t& p2) {
    float p1f = rintf(v * inv1);
    float r = fmaf(-p1f, s1, v);
    float p2f = rintf(r * inv1 * 256.0f);
    p2f = fminf(127.0f, fmaxf(-127.0f, p2f));
    p1 = (int8_t)(int)p1f;
    p2 = (int8_t)(int)p2f;
}

// ---------------------------------------------------------------------------
// max|W| reduction (order-independent => deterministic)
// ---------------------------------------------------------------------------
__global__ void max_w(const float* __restrict__ F, const float* __restrict__ NF) {
    int tid = blockIdx.x * blockDim.x + threadIdx.x;
    float m = 0.0f;
    for (int i = tid; i < NN * 64; i += gridDim.x * blockDim.x) {
        m = fmaxf(m, fabsf(F[i]));
        m = fmaxf(m, fabsf(NF[i]));
    }
    #pragma unroll
    for (int o = 16; o; o >>= 1) m = fmaxf(m, __shfl_xor_sync(~0u, m, o));
    if ((threadIdx.x & 31) == 0) atomicMax(&g_maxW, __float_as_uint(m));
}

// ---------------------------------------------------------------------------
// conv_b1: transpose W=[F|NF] -> [n][k], quantize to s8 digit pair
// ---------------------------------------------------------------------------
__global__ void conv_b1(const float* __restrict__ F, const float* __restrict__ NF) {
    __shared__ float tile[32][33];
    int k0 = blockIdx.x * 32, n0 = blockIdx.y * 32;
    int tx = threadIdx.x, ty = threadIdx.y;              // (32, 8)
    const float* src = (n0 < 64) ? F : NF;
    int nc = (n0 < 64) ? n0 : (n0 - 64);
    #pragma unroll
    for (int j = 0; j < 4; ++j) {
        int r = ty + 8 * j;
        tile[r][tx] = src[(size_t)(k0 + r) * 64 + nc + tx];
    }
    __syncthreads();
    float M = __uint_as_float(g_maxW);
    float s1 = M * (1.0f / 127.0f), inv1 = 1.0f / s1;
    #pragma unroll
    for (int j = 0; j < 4; ++j) {
        int rn = ty + 8 * j;
        float v = tile[tx][rn];                          // W[k0+tx][n0+rn]
        int8_t p1, p2;
        quantB(v, s1, inv1, p1, p2);
        size_t o = (size_t)(n0 + rn) * NN + k0 + tx;
        g_P1b1[o] = p1;
        g_P2b1[o] = p2;
    }
}

// ---------------------------------------------------------------------------
// conv_b2: quantize layer-1 output g_C1 [n][k] -> s8 digit pair
// ---------------------------------------------------------------------------
__global__ void conv_b2() {
    float M = __uint_as_float(g_maxC);
    float s1 = M * (1.0f / 127.0f), inv1 = 1.0f / s1;
    size_t i4 = (size_t)blockIdx.x * blockDim.x + threadIdx.x;  // over NN*WID/4
    float4 v = reinterpret_cast<const float4*>(g_C1)[i4];
    int8_t a1, a2, b1, b2, c1, c2, d1, d2;
    quantB(v.x, s1, inv1, a1, a2);
    quantB(v.y, s1, inv1, b1, b2);
    quantB(v.z, s1, inv1, c1, c2);
    quantB(v.w, s1, inv1, d1, d2);
    reinterpret_cast<char4*>(g_P1b2)[i4] = make_char4(a1, b1, c1, d1);
    reinterpret_cast<char4*>(g_P2b2)[i4] = make_char4(a2, b2, c2, d2);
}

// ---------------------------------------------------------------------------
// one BK=32 chunk: 8 ldmx4 + 24 IMMA (warp tile 32x32)
// ---------------------------------------------------------------------------
__device__ __forceinline__ void compute_tile(uint32_t base, uint32_t aLaneOff,
                                             uint32_t bLaneOff, int warp_m,
                                             int warp_n, int (&am)[2][4][4],
                                             int (&ac)[2][4][4]) {
    const uint32_t a1o = base + AQ1_OFF + warp_m * 1536 + aLaneOff;
    const uint32_t a2o = base + AQ2_OFF + warp_m * 1536 + aLaneOff;
    const uint32_t b1o = base + BP1_OFF + warp_n * 1536 + bLaneOff;
    const uint32_t b2o = base + BP2_OFF + warp_n * 1536 + bLaneOff;
    uint32_t q1[2][4], q2[2][4], p1[2][4], p2[2][4];
    ldmx4(q1[0], a1o);        ldmx4(q1[1], a1o + 768);
    ldmx4(q2[0], a2o);        ldmx4(q2[1], a2o + 768);
    ldmx4(p1[0], b1o);        ldmx4(p1[1], b1o + 768);
    ldmx4(p2[0], b2o);        ldmx4(p2[1], b2o + 768);
    #pragma unroll
    for (int mt = 0; mt < 2; ++mt)
        #pragma unroll
        for (int nt = 0; nt < 4; ++nt) {
            const uint32_t* b1 = &p1[nt >> 1][(nt & 1) * 2];
            const uint32_t* b2 = &p2[nt >> 1][(nt & 1) * 2];
            imma(am[mt][nt], q1[mt], b1);    // main
            imma(ac[mt][nt], q1[mt], b2);    // corr hi*lo
            imma(ac[mt][nt], q2[mt], b1);    // corr lo*hi
        }
}

// ---------------------------------------------------------------------------
// gemm_i8<LAYER>: C = A @ W. A fp32 from gmem, quantized in-register.
// LAYER==1: B digits = b1 set; epilogue -> g_C1 [n][k] fp32 + atomicMax.
// LAYER==2: B digits = b2 set; epilogue -> out fp32 [m][n].
// relu on cols<64 both layers.
// ---------------------------------------------------------------------------
template <int LAYER>
__global__ __launch_bounds__(256, 1)
void gemm_i8(const float* __restrict__ A, float* __restrict__ outp) {
    extern __shared__ char smem[];
    const uint32_t sb = s2u(smem);
    const int tid = threadIdx.x, lane = tid & 31, wid = tid >> 5;
    const int warp_m = wid >> 2, warp_n = wid & 3;
    const int m0 = blockIdx.x * 64;

    const int8_t* __restrict__ P1 = (LAYER == 1) ? g_P1b1 : g_P1b2;
    const int8_t* __restrict__ P2 = (LAYER == 1) ? g_P2b1 : g_P2b2;

    const uint32_t aLaneOff = (lane & 15) * PITCH + (lane >> 4) * 16;
    const uint32_t n16 = (lane & 7) + ((lane >> 4) << 3);
    const uint32_t bLaneOff = n16 * PITCH + ((lane >> 3) & 1) * 16;

    // staging assignments
    const int arow = tid >> 2, ac = (tid & 3) * 8;            // A: 8 fp32/thread
    const float* gA = A + (size_t)(m0 + arow) * NN + ac;
    const int brow = tid >> 1, bc = (tid & 1) * 16;           // B: 16 B/digit
    const int8_t* gB1 = P1 + (size_t)brow * NN + bc;
    const int8_t* gB2 = P2 + (size_t)brow * NN + bc;
    const uint32_t sAoff = arow * PITCH + (tid & 3) * 8;
    const uint32_t sBoff = brow * PITCH + bc;

    int am[2][4][4], acr[2][4][4];
    #pragma unroll
    for (int i = 0; i < 2; ++i)
        #pragma unroll
        for (int j = 0; j < 4; ++j)
            #pragma unroll
            for (int q = 0; q < 4; ++q) { am[i][j][q] = 0; acr[i][j][q] = 0; }

    // ---- preload tile 0 ----
    {
        float4 a0 = *reinterpret_cast<const float4*>(gA);
        float4 a1 = *reinterpret_cast<const float4*>(gA + 4);
        uint2 d1, d2;
        quantA8(a0, a1, d1, d2);
        *reinterpret_cast<uint2*>(smem + AQ1_OFF + sAoff) = d1;
        *reinterpret_cast<uint2*>(smem + AQ2_OFF + sAoff) = d2;
        *reinterpret_cast<uint4*>(smem + BP1_OFF + sBoff) =
            *reinterpret_cast<const uint4*>(gB1);
        *reinterpret_cast<uint4*>(smem + BP2_OFF + sBoff) =
            *reinterpret_cast<const uint4*>(gB2);
    }
    __syncthreads();

    // ---- main loop: 256 chunks of BK=32 ----
    #pragma unroll 1
    for (int t = 0; t < 255; ++t) {
        const int kc = (t + 1) * 32;
        float4 pa0 = *reinterpret_cast<const float4*>(gA + kc);
        float4 pa1 = *reinterpret_cast<const float4*>(gA + kc + 4);
        uint4 pb1 = *reinterpret_cast<const uint4*>(gB1 + kc);
        uint4 pb2 = *reinterpret_cast<const uint4*>(gB2 + kc);

        compute_tile(sb + (uint32_t)(t & 1) * BUF_BYTES, aLaneOff, bLaneOff,
                     warp_m, warp_n, am, acr);

        char* nb = smem + ((t + 1) & 1) * BUF_BYTES;
        uint2 d1, d2;
        quantA8(pa0, pa1, d1, d2);
        *reinterpret_cast<uint2*>(nb + AQ1_OFF + sAoff) = d1;
        *reinterpret_cast<uint2*>(nb + AQ2_OFF + sAoff) = d2;
        *reinterpret_cast<uint4*>(nb + BP1_OFF + sBoff) = pb1;
        *reinterpret_cast<uint4*>(nb + BP2_OFF + sBoff) = pb2;
        __syncthreads();
    }
    compute_tile(sb + (uint32_t)1 * BUF_BYTES, aLaneOff, bLaneOff,
                 warp_m, warp_n, am, acr);
    __syncthreads();

    // ---- epilogue:  c = 2^-21 * sB * (main + corr/256) ----
    const float Mb = __uint_as_float((LAYER == 1) ? g_maxW : g_maxC);
    const float scale = Mb * (1.0f / 127.0f) * 4.76837158203125e-07f;  // 2^-21
    const int r_base = warp_m * 32 + (lane >> 2);
    const int c_base = warp_n * 32 + (lane & 3) * 2;

    if (LAYER == 1) {
        float* sE = reinterpret_cast<float*>(smem);   // pitch 68 floats
        #pragma unroll
        for (int mt = 0; mt < 2; ++mt)
            #pragma unroll
            for (int nt = 0; nt < 4; ++nt) {
                int r = r_base + mt * 16;
                int c = c_base + nt * 8;
                float v[4];
                #pragma unroll
                for (int q = 0; q < 4; ++q)
                    v[q] = scale * ((float)am[mt][nt][q] +
                                    (float)acr[mt][nt][q] * (1.0f / 256.0f));
                if (c < 64) {
                    #pragma unroll
                    for (int q = 0; q < 4; ++q) v[q] = fmaxf(v[q], 0.0f);
                }
                sE[(c    ) * 68 + r    ] = v[0];
                sE[(c + 1) * 68 + r    ] = v[1];
                sE[(c    ) * 68 + r + 8] = v[2];
                sE[(c + 1) * 68 + r + 8] = v[3];
            }
        __syncthreads();
        const int n = tid >> 1, k0 = (tid & 1) * 32;
        const float* src = sE + n * 68 + k0;
        float* dst = g_C1 + (size_t)n * NN + m0 + k0;
        float mx = 0.0f;
        #pragma unroll
        for (int q = 0; q < 8; ++q) {
            float4 w = make_float4(src[4 * q], src[4 * q + 1],
                                   src[4 * q + 2], src[4 * q + 3]);
            mx = fmaxf(mx, fmaxf(fmaxf(fabsf(w.x), fabsf(w.y)),
                                 fmaxf(fabsf(w.z), fabsf(w.w))));
            reinterpret_cast<float4*>(dst)[q] = w;
        }
        #pragma unroll
        for (int o = 16; o; o >>= 1) mx = fmaxf(mx, __shfl_xor_sync(~0u, mx, o));
        if (lane == 0) atomicMax(&g_maxC, __float_as_uint(mx));
    } else {
        #pragma unroll
        for (int mt = 0; mt < 2; ++mt)
            #pragma unroll
            for (int nt = 0; nt < 4; ++nt) {
                int r = m0 + r_base + mt * 16;
                int c = c_base + nt * 8;
                float v[4];
                #pragma unroll
                for (int q = 0; q < 4; ++q)
                    v[q] = scale * ((float)am[mt][nt][q] +
                                    (float)acr[mt][nt][q] * (1.0f / 256.0f));
                if (c < 64) {
                    #pragma unroll
                    for (int q = 0; q < 4; ++q) v[q] = fmaxf(v[q], 0.0f);
                }
                *reinterpret_cast<float2*>(&outp[(size_t)r * WID + c]) =
                    make_float2(v[0], v[1]);
                *reinterpret_cast<float2*>(&outp[(size_t)(r + 8) * WID + c]) =
                    make_float2(v[2], v[3]);
            }
    }
}

// ---------------------------------------------------------------------------
// launch chain. Graph-capturable, allocation-free.
// ---------------------------------------------------------------------------
extern "C" void kernel_launch(void* const* d_in, const int* in_sizes, int n_in,
                              void* d_out, int out_size) {
    const float* A  = (const float*)d_in[0];
    const float* F  = (const float*)d_in[1];
    const float* NF = (const float*)d_in[2];
    float* out = (float*)d_out;

    max_w<<<256, 256>>>(F, NF);
    conv_b1<<<dim3(NN / 32, WID / 32), dim3(32, 8)>>>(F, NF);
    gemm_i8<1><<<NN / 64, 256, SMEM_GEMM>>>(A, nullptr);
    conv_b2<<<(WID * NN / 4) / 256, 256>>>();
    gemm_i8<2><<<NN / 64, 256, SMEM_GEMM>>>(A, out);
}

// round 9
// speedup vs baseline: 1.8759x; 1.8759x over previous
#include <cuda_runtime.h>
#include <cuda_fp16.h>
#include <cstdint>

// ---------------------------------------------------------------------------
// out = concat( relu(A@relu(A@F)), A@(A@NF) ), N=8192, D=E=64.
// Both layers: C[8192,128] = A[8192,8192] @ W[8192,128], relu on cols<64.
// Path: HMMA f16 (m16n8k16.f32.f16.f16.f32), TWO-term split:
//   A (in [0,2^-13), scaled by 2^13):  a' = ah + al/2048   (fp16 digits)
//   B:                                  b ~= bh             (single fp16)
//   C = ( Ah@Bh + (Al@Bh)/2048 ) / 8192,  fp32 accumulate.
// Error ~2^-12 per layer (B rounding) => total ~3e-4 rms, threshold 1e-3.
// ---------------------------------------------------------------------------

constexpr int NN  = 8192;
constexpr int WID = 128;

// smem tiles: fp16 rows of 32 elems (64B) at pitch 80B (conflict-free ldmatrix)
constexpr int PITCH  = 80;
constexpr int AH_OFF = 0;                    // 64 rows  -> 5120 B
constexpr int AL_OFF = 5120;                 // 64 rows
constexpr int BH_OFF = 10240;                // 128 rows -> 10240 B
constexpr int BUF_BYTES = 20480;
constexpr int SMEM_GEMM = 2 * BUF_BYTES;     // 40960 (>= 34816 epilogue stage)

// B operands, [n][k] (k contiguous) == col-major B for mma.
__device__ __align__(16) __half g_B1[(size_t)WID * NN];
__device__ __align__(16) __half g_B2[(size_t)WID * NN];

// ---------------------------------------------------------------------------
// helpers
// ---------------------------------------------------------------------------
__device__ __forceinline__ uint32_t s2u(const void* p) {
    uint32_t a;
    asm("{ .reg .u64 t; cvta.to.shared.u64 t, %1; cvt.u32.u64 %0, t; }"
        : "=r"(a) : "l"(p));
    return a;
}

__device__ __forceinline__ void ldmx4(uint32_t* r, uint32_t addr) {
    asm volatile("ldmatrix.sync.aligned.m8n8.x4.shared.b16 {%0,%1,%2,%3}, [%4];"
                 : "=r"(r[0]), "=r"(r[1]), "=r"(r[2]), "=r"(r[3]) : "r"(addr));
}

__device__ __forceinline__ void hmma(float* c, const uint32_t* a,
                                     const uint32_t* b) {
    asm volatile(
        "mma.sync.aligned.m16n8k16.row.col.f32.f16.f16.f32 "
        "{%0,%1,%2,%3}, {%4,%5,%6,%7}, {%8,%9}, {%0,%1,%2,%3};"
        : "+f"(c[0]), "+f"(c[1]), "+f"(c[2]), "+f"(c[3])
        : "r"(a[0]), "r"(a[1]), "r"(a[2]), "r"(a[3]), "r"(b[0]), "r"(b[1]));
}

__device__ __forceinline__ uint32_t packh(__half a, __half b) {
    __half2 t = __halves2half2(a, b);
    return *reinterpret_cast<uint32_t*>(&t);
}

// split 8 fp32 A elems: a' = a*8192 -> fp16 hi + fp16 lo (lo scaled by 2048)
__device__ __forceinline__ void splitA8(float4 x, float4 y, uint4& h, uint4& l) {
    float v[8] = {x.x, x.y, x.z, x.w, y.x, y.y, y.z, y.w};
    uint32_t hw[4], lw[4];
    #pragma unroll
    for (int i = 0; i < 4; ++i) {
        float a = v[2 * i] * 8192.0f, b = v[2 * i + 1] * 8192.0f;
        __half ha = __float2half_rn(a);
        __half hb = __float2half_rn(b);
        float ra = (a - __half2float(ha)) * 2048.0f;
        float rb = (b - __half2float(hb)) * 2048.0f;
        hw[i] = packh(ha, hb);
        lw[i] = packh(__float2half_rn(ra), __float2half_rn(rb));
    }
    h = make_uint4(hw[0], hw[1], hw[2], hw[3]);
    l = make_uint4(lw[0], lw[1], lw[2], lw[3]);
}

// ---------------------------------------------------------------------------
// conv_b1: transpose W=[F|NF] ([8192,64] each) -> g_B1 [n][k] fp16
// ---------------------------------------------------------------------------
__global__ void conv_b1(const float* __restrict__ F, const float* __restrict__ NF) {
    __shared__ float tile[32][33];
    int k0 = blockIdx.x * 32, n0 = blockIdx.y * 32;
    int tx = threadIdx.x, ty = threadIdx.y;              // (32, 8)
    const float* src = (n0 < 64) ? F : NF;
    int nc = (n0 < 64) ? n0 : (n0 - 64);
    #pragma unroll
    for (int j = 0; j < 4; ++j) {
        int r = ty + 8 * j;
        tile[r][tx] = src[(size_t)(k0 + r) * 64 + nc + tx];
    }
    __syncthreads();
    #pragma unroll
    for (int j = 0; j < 4; ++j) {
        int rn = ty + 8 * j;
        float v = tile[tx][rn];                          // W[k0+tx][n0+rn]
        g_B1[(size_t)(n0 + rn) * NN + k0 + tx] = __float2half_rn(v);
    }
}

// ---------------------------------------------------------------------------
// one BK=32 chunk: 12 ldmx4 + 32 HMMA (warp tile 32x32, 2 terms)
// ---------------------------------------------------------------------------
__device__ __forceinline__ void compute_tile(uint32_t base, uint32_t aLaneOff,
                                             uint32_t bLaneOff, int warp_m,
                                             int warp_n, float (&am)[2][4][4],
                                             float (&ac)[2][4][4]) {
    const uint32_t aho = base + AH_OFF + warp_m * 2560 + aLaneOff;
    const uint32_t alo = base + AL_OFF + warp_m * 2560 + aLaneOff;
    const uint32_t bho = base + BH_OFF + warp_n * 2560 + bLaneOff;
    #pragma unroll
    for (int ks = 0; ks < 2; ++ks) {
        uint32_t ah[2][4], al[2][4], bh[2][4];
        ldmx4(ah[0], aho + ks * 32);
        ldmx4(ah[1], aho + ks * 32 + 1280);
        ldmx4(al[0], alo + ks * 32);
        ldmx4(al[1], alo + ks * 32 + 1280);
        ldmx4(bh[0], bho + ks * 32);
        ldmx4(bh[1], bho + ks * 32 + 1280);
        #pragma unroll
        for (int mt = 0; mt < 2; ++mt)
            #pragma unroll
            for (int nt = 0; nt < 4; ++nt) {
                const uint32_t* b2 = &bh[nt >> 1][(nt & 1) * 2];
                hmma(am[mt][nt], ah[mt], b2);    // main
                hmma(ac[mt][nt], al[mt], b2);    // correction (x 1/2048)
            }
    }
}

// ---------------------------------------------------------------------------
// gemm_f16<LAYER>: C = A @ W.  A fp32 from gmem, split to 2 fp16 digits
// in-register during staging. B single fp16 digit from g_B1/g_B2.
// LAYER==1: epilogue -> g_B2 [n][k] fp16 (relu cols<64, transposed)
// LAYER==2: epilogue -> out fp32 [m][n]  (relu cols<64)
// ---------------------------------------------------------------------------
template <int LAYER>
__global__ __launch_bounds__(256, 1)
void gemm_f16(const float* __restrict__ A, float* __restrict__ outp) {
    extern __shared__ char smem[];
    const uint32_t sb = s2u(smem);
    const int tid = threadIdx.x, lane = tid & 31, wid = tid >> 5;
    const int warp_m = wid >> 2, warp_n = wid & 3;
    const int m0 = blockIdx.x * 64;

    const __half* __restrict__ B = (LAYER == 1) ? g_B1 : g_B2;

    // ldmatrix lane offsets
    const uint32_t aLaneOff = (lane & 15) * PITCH + (lane >> 4) * 16;
    const uint32_t n16 = (lane & 7) + ((lane >> 4) << 3);
    const uint32_t bLaneOff = n16 * PITCH + ((lane >> 3) & 1) * 16;

    // staging assignments
    const int arow = tid >> 2, acl = (tid & 3) * 8;       // A: 8 fp32/thread
    const float* gA = A + (size_t)(m0 + arow) * NN + acl;
    const int brow = tid >> 1, bcl = (tid & 1) * 16;      // B: 16 f16/thread
    const __half* gB = B + (size_t)brow * NN + bcl;
    const uint32_t sAoff = arow * PITCH + (tid & 3) * 16;
    const uint32_t sBoff = brow * PITCH + (tid & 1) * 32;

    float am[2][4][4], ac[2][4][4];
    #pragma unroll
    for (int i = 0; i < 2; ++i)
        #pragma unroll
        for (int j = 0; j < 4; ++j)
            #pragma unroll
            for (int q = 0; q < 4; ++q) { am[i][j][q] = 0.0f; ac[i][j][q] = 0.0f; }

    // ---- preload tile 0 ----
    {
        float4 a0 = *reinterpret_cast<const float4*>(gA);
        float4 a1 = *reinterpret_cast<const float4*>(gA + 4);
        uint4 h, l;
        splitA8(a0, a1, h, l);
        *reinterpret_cast<uint4*>(smem + AH_OFF + sAoff) = h;
        *reinterpret_cast<uint4*>(smem + AL_OFF + sAoff) = l;
        uint4 b0 = *reinterpret_cast<const uint4*>(gB);
        uint4 b1 = *reinterpret_cast<const uint4*>(gB + 8);
        *reinterpret_cast<uint4*>(smem + BH_OFF + sBoff)      = b0;
        *reinterpret_cast<uint4*>(smem + BH_OFF + sBoff + 16) = b1;
    }
    __syncthreads();

    // ---- main loop: 256 chunks of BK=32 ----
    #pragma unroll 1
    for (int t = 0; t < 255; ++t) {
        const int kc = (t + 1) * 32;
        float4 pa0 = *reinterpret_cast<const float4*>(gA + kc);
        float4 pa1 = *reinterpret_cast<const float4*>(gA + kc + 4);
        uint4 pb0 = *reinterpret_cast<const uint4*>(gB + kc);
        uint4 pb1 = *reinterpret_cast<const uint4*>(gB + kc + 8);

        compute_tile(sb + (uint32_t)(t & 1) * BUF_BYTES, aLaneOff, bLaneOff,
                     warp_m, warp_n, am, ac);

        char* nb = smem + ((t + 1) & 1) * BUF_BYTES;
        uint4 h, l;
        splitA8(pa0, pa1, h, l);
        *reinterpret_cast<uint4*>(nb + AH_OFF + sAoff) = h;
        *reinterpret_cast<uint4*>(nb + AL_OFF + sAoff) = l;
        *reinterpret_cast<uint4*>(nb + BH_OFF + sBoff)      = pb0;
        *reinterpret_cast<uint4*>(nb + BH_OFF + sBoff + 16) = pb1;
        __syncthreads();
    }
    compute_tile(sb + (uint32_t)1 * BUF_BYTES, aLaneOff, bLaneOff,
                 warp_m, warp_n, am, ac);
    __syncthreads();

    // ---- epilogue: v = (main + corr/2048) / 8192, relu cols<64 ----
    const int r_base = warp_m * 32 + (lane >> 2);
    const int c_base = warp_n * 32 + (lane & 3) * 2;
    constexpr float INV_CORR = 1.0f / 2048.0f;
    constexpr float INV_SC   = 1.0f / 8192.0f;

    if (LAYER == 1) {
        // stage fp32 [n][k] in smem (pitch 68 floats), then coalesced f16 out
        float* sE = reinterpret_cast<float*>(smem);
        #pragma unroll
        for (int mt = 0; mt < 2; ++mt)
            #pragma unroll
            for (int nt = 0; nt < 4; ++nt) {
                int r = r_base + mt * 16;
                int c = c_base + nt * 8;
                float v[4];
                #pragma unroll
                for (int q = 0; q < 4; ++q)
                    v[q] = fmaf(ac[mt][nt][q], INV_CORR, am[mt][nt][q]) * INV_SC;
                if (c < 64) {
                    #pragma unroll
                    for (int q = 0; q < 4; ++q) v[q] = fmaxf(v[q], 0.0f);
                }
                sE[(c    ) * 68 + r    ] = v[0];
                sE[(c + 1) * 68 + r    ] = v[1];
                sE[(c    ) * 68 + r + 8] = v[2];
                sE[(c + 1) * 68 + r + 8] = v[3];
            }
        __syncthreads();
        const int n = tid >> 1, k0 = (tid & 1) * 32;
        const float* src = sE + n * 68 + k0;
        uint32_t w[16];
        #pragma unroll
        for (int j = 0; j < 16; ++j)
            w[j] = packh(__float2half_rn(src[2 * j]),
                         __float2half_rn(src[2 * j + 1]));
        uint4* dst = reinterpret_cast<uint4*>(g_B2 + (size_t)n * NN + m0 + k0);
        #pragma unroll
        for (int q = 0; q < 4; ++q)
            dst[q] = make_uint4(w[4 * q], w[4 * q + 1], w[4 * q + 2], w[4 * q + 3]);
    } else {
        #pragma unroll
        for (int mt = 0; mt < 2; ++mt)
            #pragma unroll
            for (int nt = 0; nt < 4; ++nt) {
                int r = m0 + r_base + mt * 16;
                int c = c_base + nt * 8;
                float v[4];
                #pragma unroll
                for (int q = 0; q < 4; ++q)
                    v[q] = fmaf(ac[mt][nt][q], INV_CORR, am[mt][nt][q]) * INV_SC;
                if (c < 64) {
                    #pragma unroll
                    for (int q = 0; q < 4; ++q) v[q] = fmaxf(v[q], 0.0f);
                }
                *reinterpret_cast<float2*>(&outp[(size_t)r * WID + c]) =
                    make_float2(v[0], v[1]);
                *reinterpret_cast<float2*>(&outp[(size_t)(r + 8) * WID + c]) =
                    make_float2(v[2], v[3]);
            }
    }
}

// ---------------------------------------------------------------------------
// launch: conv_b1 -> layer1 -> layer2. Graph-capturable, allocation-free,
// fully deterministic (no atomics).
// ---------------------------------------------------------------------------
extern "C" void kernel_launch(void* const* d_in, const int* in_sizes, int n_in,
                              void* d_out, int out_size) {
    const float* A  = (const float*)d_in[0];
    const float* F  = (const float*)d_in[1];
    const float* NF = (const float*)d_in[2];
    float* out = (float*)d_out;

    cudaFuncSetAttribute(gemm_f16<1>, cudaFuncAttributeMaxDynamicSharedMemorySize, SMEM_GEMM);
    cudaFuncSetAttribute(gemm_f16<2>, cudaFuncAttributeMaxDynamicSharedMemorySize, SMEM_GEMM);

    conv_b1<<<dim3(NN / 32, WID / 32), dim3(32, 8)>>>(F, NF);
    gemm_f16<1><<<NN / 64, 256, SMEM_GEMM>>>(A, nullptr);
    gemm_f16<2><<<NN / 64, 256, SMEM_GEMM>>>(A, out);
}

// round 10
// speedup vs baseline: 1.9402x; 1.0343x over previous
#include <cuda_runtime.h>
#include <cuda_fp16.h>
#include <cstdint>

// ---------------------------------------------------------------------------
// out = concat( relu(A@relu(A@F)), A@(A@NF) ), N=8192, D=E=64.
// Both layers: C[8192,128] = A[8192,8192] @ W[8192,128], relu on cols<64.
// Path: single-term fp16 HMMA (m16n8k16.f32.f16.f16.f32).
//   A in [0, 2^-13): scaled by 2^13 -> [0,1), one fp16 digit (all normal).
//   B ~ N(0,1): one fp16 digit.
//   C = (Ah@Bh) / 8192, fp32 accumulate.
// Error: eps_A ~ eps_B ~ 2^-12.3/layer -> total ~2.8e-4 (threshold 1e-3).
// ---------------------------------------------------------------------------

constexpr int NN  = 8192;
constexpr int WID = 128;

// smem tiles: fp16 rows of 32 elems (64B) at pitch 80B (conflict-free ldmatrix)
constexpr int PITCH  = 80;
constexpr int AH_OFF = 0;                    // 64 rows  -> 5120 B
constexpr int BH_OFF = 5120;                 // 128 rows -> 10240 B
constexpr int BUF_BYTES = 15360;
constexpr int SMEM_GEMM = 34816;             // max(2*BUF_BYTES, epilogue stage)

// B operands, [n][k] (k contiguous) == col-major B for mma.
__device__ __align__(16) __half g_B1[(size_t)WID * NN];
__device__ __align__(16) __half g_B2[(size_t)WID * NN];

// ---------------------------------------------------------------------------
// helpers
// ---------------------------------------------------------------------------
__device__ __forceinline__ uint32_t s2u(const void* p) {
    uint32_t a;
    asm("{ .reg .u64 t; cvta.to.shared.u64 t, %1; cvt.u32.u64 %0, t; }"
        : "=r"(a) : "l"(p));
    return a;
}

__device__ __forceinline__ void ldmx4(uint32_t* r, uint32_t addr) {
    asm volatile("ldmatrix.sync.aligned.m8n8.x4.shared.b16 {%0,%1,%2,%3}, [%4];"
                 : "=r"(r[0]), "=r"(r[1]), "=r"(r[2]), "=r"(r[3]) : "r"(addr));
}

__device__ __forceinline__ void hmma(float* c, const uint32_t* a,
                                     const uint32_t* b) {
    asm volatile(
        "mma.sync.aligned.m16n8k16.row.col.f32.f16.f16.f32 "
        "{%0,%1,%2,%3}, {%4,%5,%6,%7}, {%8,%9}, {%0,%1,%2,%3};"
        : "+f"(c[0]), "+f"(c[1]), "+f"(c[2]), "+f"(c[3])
        : "r"(a[0]), "r"(a[1]), "r"(a[2]), "r"(a[3]), "r"(b[0]), "r"(b[1]));
}

__device__ __forceinline__ uint32_t packh(__half a, __half b) {
    __half2 t = __halves2half2(a, b);
    return *reinterpret_cast<uint32_t*>(&t);
}

// convert 8 fp32 A elems (scaled by 2^13) -> 8 fp16
__device__ __forceinline__ void cvtA8(float4 x, float4 y, uint4& h) {
    h = make_uint4(
        packh(__float2half_rn(x.x * 8192.0f), __float2half_rn(x.y * 8192.0f)),
        packh(__float2half_rn(x.z * 8192.0f), __float2half_rn(x.w * 8192.0f)),
        packh(__float2half_rn(y.x * 8192.0f), __float2half_rn(y.y * 8192.0f)),
        packh(__float2half_rn(y.z * 8192.0f), __float2half_rn(y.w * 8192.0f)));
}

// ---------------------------------------------------------------------------
// conv_b1: transpose W=[F|NF] ([8192,64] each) -> g_B1 [n][k] fp16
// ---------------------------------------------------------------------------
__global__ void conv_b1(const float* __restrict__ F, const float* __restrict__ NF) {
    __shared__ float tile[32][33];
    int k0 = blockIdx.x * 32, n0 = blockIdx.y * 32;
    int tx = threadIdx.x, ty = threadIdx.y;              // (32, 8)
    const float* src = (n0 < 64) ? F : NF;
    int nc = (n0 < 64) ? n0 : (n0 - 64);
    #pragma unroll
    for (int j = 0; j < 4; ++j) {
        int r = ty + 8 * j;
        tile[r][tx] = src[(size_t)(k0 + r) * 64 + nc + tx];
    }
    __syncthreads();
    #pragma unroll
    for (int j = 0; j < 4; ++j) {
        int rn = ty + 8 * j;
        float v = tile[tx][rn];                          // W[k0+tx][n0+rn]
        g_B1[(size_t)(n0 + rn) * NN + k0 + tx] = __float2half_rn(v);
    }
}

// ---------------------------------------------------------------------------
// one BK=32 chunk: 8 ldmx4 + 16 HMMA (warp tile 32x32, single term)
// ---------------------------------------------------------------------------
__device__ __forceinline__ void compute_tile(uint32_t base, uint32_t aLaneOff,
                                             uint32_t bLaneOff, int warp_m,
                                             int warp_n, float (&am)[2][4][4]) {
    const uint32_t aho = base + AH_OFF + warp_m * 2560 + aLaneOff;
    const uint32_t bho = base + BH_OFF + warp_n * 2560 + bLaneOff;
    #pragma unroll
    for (int ks = 0; ks < 2; ++ks) {
        uint32_t ah[2][4], bh[2][4];
        ldmx4(ah[0], aho + ks * 32);
        ldmx4(ah[1], aho + ks * 32 + 1280);
        ldmx4(bh[0], bho + ks * 32);
        ldmx4(bh[1], bho + ks * 32 + 1280);
        #pragma unroll
        for (int mt = 0; mt < 2; ++mt)
            #pragma unroll
            for (int nt = 0; nt < 4; ++nt)
                hmma(am[mt][nt], ah[mt], &bh[nt >> 1][(nt & 1) * 2]);
    }
}

// ---------------------------------------------------------------------------
// gemm_f16<LAYER>: C = A @ W.  A fp32 from gmem, converted to fp16 in-register
// during staging. B fp16 from g_B1/g_B2.
// LAYER==1: epilogue -> g_B2 [n][k] fp16 (relu cols<64, transposed)
// LAYER==2: epilogue -> out fp32 [m][n]  (relu cols<64)
// ---------------------------------------------------------------------------
template <int LAYER>
__global__ __launch_bounds__(256, 1)
void gemm_f16(const float* __restrict__ A, float* __restrict__ outp) {
    extern __shared__ char smem[];
    const uint32_t sb = s2u(smem);
    const int tid = threadIdx.x, lane = tid & 31, wid = tid >> 5;
    const int warp_m = wid >> 2, warp_n = wid & 3;
    const int m0 = blockIdx.x * 64;

    const __half* __restrict__ B = (LAYER == 1) ? g_B1 : g_B2;

    // ldmatrix lane offsets
    const uint32_t aLaneOff = (lane & 15) * PITCH + (lane >> 4) * 16;
    const uint32_t n16 = (lane & 7) + ((lane >> 4) << 3);
    const uint32_t bLaneOff = n16 * PITCH + ((lane >> 3) & 1) * 16;

    // staging assignments
    const int arow = tid >> 2, acl = (tid & 3) * 8;       // A: 8 fp32/thread
    const float* gA = A + (size_t)(m0 + arow) * NN + acl;
    const int brow = tid >> 1, bcl = (tid & 1) * 16;      // B: 16 f16/thread
    const __half* gB = B + (size_t)brow * NN + bcl;
    const uint32_t sAoff = arow * PITCH + (tid & 3) * 16;
    const uint32_t sBoff = brow * PITCH + (tid & 1) * 32;

    float am[2][4][4];
    #pragma unroll
    for (int i = 0; i < 2; ++i)
        #pragma unroll
        for (int j = 0; j < 4; ++j)
            #pragma unroll
            for (int q = 0; q < 4; ++q) am[i][j][q] = 0.0f;

    // ---- preload tile 0 ----
    {
        float4 a0 = *reinterpret_cast<const float4*>(gA);
        float4 a1 = *reinterpret_cast<const float4*>(gA + 4);
        uint4 h;
        cvtA8(a0, a1, h);
        *reinterpret_cast<uint4*>(smem + AH_OFF + sAoff) = h;
        uint4 b0 = *reinterpret_cast<const uint4*>(gB);
        uint4 b1 = *reinterpret_cast<const uint4*>(gB + 8);
        *reinterpret_cast<uint4*>(smem + BH_OFF + sBoff)      = b0;
        *reinterpret_cast<uint4*>(smem + BH_OFF + sBoff + 16) = b1;
    }
    __syncthreads();

    // ---- main loop: 256 chunks of BK=32 ----
    #pragma unroll 1
    for (int t = 0; t < 255; ++t) {
        const int kc = (t + 1) * 32;
        float4 pa0 = *reinterpret_cast<const float4*>(gA + kc);
        float4 pa1 = *reinterpret_cast<const float4*>(gA + kc + 4);
        uint4 pb0 = *reinterpret_cast<const uint4*>(gB + kc);
        uint4 pb1 = *reinterpret_cast<const uint4*>(gB + kc + 8);

        compute_tile(sb + (uint32_t)(t & 1) * BUF_BYTES, aLaneOff, bLaneOff,
                     warp_m, warp_n, am);

        char* nb = smem + ((t + 1) & 1) * BUF_BYTES;
        uint4 h;
        cvtA8(pa0, pa1, h);
        *reinterpret_cast<uint4*>(nb + AH_OFF + sAoff) = h;
        *reinterpret_cast<uint4*>(nb + BH_OFF + sBoff)      = pb0;
        *reinterpret_cast<uint4*>(nb + BH_OFF + sBoff + 16) = pb1;
        __syncthreads();
    }
    compute_tile(sb + (uint32_t)1 * BUF_BYTES, aLaneOff, bLaneOff,
                 warp_m, warp_n, am);
    __syncthreads();

    // ---- epilogue: v = main / 8192, relu cols<64 ----
    const int r_base = warp_m * 32 + (lane >> 2);
    const int c_base = warp_n * 32 + (lane & 3) * 2;
    constexpr float INV_SC = 1.0f / 8192.0f;

    if (LAYER == 1) {
        // stage fp32 [n][k] in smem (pitch 68 floats), then coalesced f16 out
        float* sE = reinterpret_cast<float*>(smem);
        #pragma unroll
        for (int mt = 0; mt < 2; ++mt)
            #pragma unroll
            for (int nt = 0; nt < 4; ++nt) {
                int r = r_base + mt * 16;
                int c = c_base + nt * 8;
                float v[4];
                #pragma unroll
                for (int q = 0; q < 4; ++q) v[q] = am[mt][nt][q] * INV_SC;
                if (c < 64) {
                    #pragma unroll
                    for (int q = 0; q < 4; ++q) v[q] = fmaxf(v[q], 0.0f);
                }
                sE[(c    ) * 68 + r    ] = v[0];
                sE[(c + 1) * 68 + r    ] = v[1];
                sE[(c    ) * 68 + r + 8] = v[2];
                sE[(c + 1) * 68 + r + 8] = v[3];
            }
        __syncthreads();
        const int n = tid >> 1, k0 = (tid & 1) * 32;
        const float* src = sE + n * 68 + k0;
        uint32_t w[16];
        #pragma unroll
        for (int j = 0; j < 16; ++j)
            w[j] = packh(__float2half_rn(src[2 * j]),
                         __float2half_rn(src[2 * j + 1]));
        uint4* dst = reinterpret_cast<uint4*>(g_B2 + (size_t)n * NN + m0 + k0);
        #pragma unroll
        for (int q = 0; q < 4; ++q)
            dst[q] = make_uint4(w[4 * q], w[4 * q + 1], w[4 * q + 2], w[4 * q + 3]);
    } else {
        #pragma unroll
        for (int mt = 0; mt < 2; ++mt)
            #pragma unroll
            for (int nt = 0; nt < 4; ++nt) {
                int r = m0 + r_base + mt * 16;
                int c = c_base + nt * 8;
                float v[4];
                #pragma unroll
                for (int q = 0; q < 4; ++q) v[q] = am[mt][nt][q] * INV_SC;
                if (c < 64) {
                    #pragma unroll
                    for (int q = 0; q < 4; ++q) v[q] = fmaxf(v[q], 0.0f);
                }
                *reinterpret_cast<float2*>(&outp[(size_t)r * WID + c]) =
                    make_float2(v[0], v[1]);
                *reinterpret_cast<float2*>(&outp[(size_t)(r + 8) * WID + c]) =
                    make_float2(v[2], v[3]);
            }
    }
}

// ---------------------------------------------------------------------------
// launch: conv_b1 -> layer1 -> layer2. Graph-capturable, allocation-free,
// deterministic (no atomics).
// ---------------------------------------------------------------------------
extern "C" void kernel_launch(void* const* d_in, const int* in_sizes, int n_in,
                              void* d_out, int out_size) {
    const float* A  = (const float*)d_in[0];
    const float* F  = (const float*)d_in[1];
    const float* NF = (const float*)d_in[2];
    float* out = (float*)d_out;

    cudaFuncSetAttribute(gemm_f16<1>, cudaFuncAttributeMaxDynamicSharedMemorySize, SMEM_GEMM);
    cudaFuncSetAttribute(gemm_f16<2>, cudaFuncAttributeMaxDynamicSharedMemorySize, SMEM_GEMM);

    conv_b1<<<dim3(NN / 32, WID / 32), dim3(32, 8)>>>(F, NF);
    gemm_f16<1><<<NN / 64, 256, SMEM_GEMM>>>(A, nullptr);
    gemm_f16<2><<<NN / 64, 256, SMEM_GEMM>>>(A, out);
}

// round 11
// speedup vs baseline: 3.6556x; 1.8841x over previous
#include <cuda_runtime.h>
#include <cuda_fp16.h>
#include <cstdint>

// ---------------------------------------------------------------------------
// out = concat( relu(A@relu(A@F)), A@(A@NF) ), N=8192, D=E=64.
// Both layers: C[8192,128] = A[8192,8192] @ W[8192,128], relu on cols<64.
// Path: single-digit fp16 HMMA + cp.async 4-stage pipeline.
//   A pre-converted to fp16 (scaled by 2^13 -> [0,1), all normal).
//   C = (Ah@Bh) / 8192, fp32 accumulate.  Error ~2e-4 total (thresh 1e-3).
// ---------------------------------------------------------------------------

constexpr int NN  = 8192;
constexpr int WID = 128;

// smem stage: fp16 rows of 32 elems (64B) at pitch 80B (16B-aligned,
// conflict-free ldmatrix).  A: 64 rows, B: 128 rows.
constexpr int PITCH  = 80;
constexpr int AH_OFF = 0;                    // 5120 B
constexpr int BH_OFF = 5120;                 // 10240 B
constexpr int BUF_BYTES = 15360;
constexpr int NSTAGE = 4;
constexpr int SMEM_GEMM = NSTAGE * BUF_BYTES;   // 61440 (>= 34816 epilogue)

__device__ __align__(16) __half g_Ah[(size_t)NN * NN];   // A * 2^13, fp16
__device__ __align__(16) __half g_B1[(size_t)WID * NN];  // [n][k]
__device__ __align__(16) __half g_B2[(size_t)WID * NN];

// ---------------------------------------------------------------------------
// helpers
// ---------------------------------------------------------------------------
__device__ __forceinline__ uint32_t s2u(const void* p) {
    uint32_t a;
    asm("{ .reg .u64 t; cvta.to.shared.u64 t, %1; cvt.u32.u64 %0, t; }"
        : "=r"(a) : "l"(p));
    return a;
}

__device__ __forceinline__ void ldmx4(uint32_t* r, uint32_t addr) {
    asm volatile("ldmatrix.sync.aligned.m8n8.x4.shared.b16 {%0,%1,%2,%3}, [%4];"
                 : "=r"(r[0]), "=r"(r[1]), "=r"(r[2]), "=r"(r[3]) : "r"(addr));
}

__device__ __forceinline__ void hmma(float* c, const uint32_t* a,
                                     const uint32_t* b) {
    asm volatile(
        "mma.sync.aligned.m16n8k16.row.col.f32.f16.f16.f32 "
        "{%0,%1,%2,%3}, {%4,%5,%6,%7}, {%8,%9}, {%0,%1,%2,%3};"
        : "+f"(c[0]), "+f"(c[1]), "+f"(c[2]), "+f"(c[3])
        : "r"(a[0]), "r"(a[1]), "r"(a[2]), "r"(a[3]), "r"(b[0]), "r"(b[1]));
}

__device__ __forceinline__ void cp16(uint32_t saddr, const void* gaddr) {
    asm volatile("cp.async.cg.shared.global [%0], [%1], 16;"
                 :: "r"(saddr), "l"(gaddr) : "memory");
}
#define CP_COMMIT() asm volatile("cp.async.commit_group;" ::: "memory")
#define CP_WAIT2()  asm volatile("cp.async.wait_group 2;" ::: "memory")

__device__ __forceinline__ uint32_t packh(__half a, __half b) {
    __half2 t = __halves2half2(a, b);
    return *reinterpret_cast<uint32_t*>(&t);
}

// ---------------------------------------------------------------------------
// conv_a: A fp32 -> fp16 * 2^13   (8 elems / thread)
// ---------------------------------------------------------------------------
__global__ __launch_bounds__(256) void conv_a(const float* __restrict__ A) {
    size_t i = (size_t)blockIdx.x * 256 + threadIdx.x;
    const float4* p = reinterpret_cast<const float4*>(A) + i * 2;
    float4 a = p[0], b = p[1];
    uint4 h = make_uint4(
        packh(__float2half_rn(a.x * 8192.0f), __float2half_rn(a.y * 8192.0f)),
        packh(__float2half_rn(a.z * 8192.0f), __float2half_rn(a.w * 8192.0f)),
        packh(__float2half_rn(b.x * 8192.0f), __float2half_rn(b.y * 8192.0f)),
        packh(__float2half_rn(b.z * 8192.0f), __float2half_rn(b.w * 8192.0f)));
    reinterpret_cast<uint4*>(g_Ah)[i] = h;
}

// ---------------------------------------------------------------------------
// conv_b1: transpose W=[F|NF] ([8192,64] each) -> g_B1 [n][k] fp16
// ---------------------------------------------------------------------------
__global__ void conv_b1(const float* __restrict__ F, const float* __restrict__ NF) {
    __shared__ float tile[32][33];
    int k0 = blockIdx.x * 32, n0 = blockIdx.y * 32;
    int tx = threadIdx.x, ty = threadIdx.y;              // (32, 8)
    const float* src = (n0 < 64) ? F : NF;
    int nc = (n0 < 64) ? n0 : (n0 - 64);
    #pragma unroll
    for (int j = 0; j < 4; ++j) {
        int r = ty + 8 * j;
        tile[r][tx] = src[(size_t)(k0 + r) * 64 + nc + tx];
    }
    __syncthreads();
    #pragma unroll
    for (int j = 0; j < 4; ++j) {
        int rn = ty + 8 * j;
        g_B1[(size_t)(n0 + rn) * NN + k0 + tx] = __float2half_rn(tile[tx][rn]);
    }
}

// ---------------------------------------------------------------------------
// one BK=32 chunk: 8 ldmx4 + 16 HMMA (warp tile 32x32)
// ---------------------------------------------------------------------------
__device__ __forceinline__ void compute_tile(uint32_t base, uint32_t aLaneOff,
                                             uint32_t bLaneOff, int warp_m,
                                             int warp_n, float (&am)[2][4][4]) {
    const uint32_t aho = base + AH_OFF + warp_m * 2560 + aLaneOff;
    const uint32_t bho = base + BH_OFF + warp_n * 2560 + bLaneOff;
    #pragma unroll
    for (int ks = 0; ks < 2; ++ks) {
        uint32_t ah[2][4], bh[2][4];
        ldmx4(ah[0], aho + ks * 32);
        ldmx4(ah[1], aho + ks * 32 + 1280);
        ldmx4(bh[0], bho + ks * 32);
        ldmx4(bh[1], bho + ks * 32 + 1280);
        #pragma unroll
        for (int mt = 0; mt < 2; ++mt)
            #pragma unroll
            for (int nt = 0; nt < 4; ++nt)
                hmma(am[mt][nt], ah[mt], &bh[nt >> 1][(nt & 1) * 2]);
    }
}

// ---------------------------------------------------------------------------
// gemm_f16<LAYER>: C = A @ W via cp.async 4-stage pipeline.
// LAYER==1: epilogue -> g_B2 [n][k] fp16 (relu cols<64, transposed)
// LAYER==2: epilogue -> out fp32 [m][n]  (relu cols<64)
// ---------------------------------------------------------------------------
template <int LAYER>
__global__ __launch_bounds__(256, 1)
void gemm_f16(float* __restrict__ outp) {
    extern __shared__ char smem[];
    const uint32_t sb = s2u(smem);
    const int tid = threadIdx.x, lane = tid & 31, wid = tid >> 5;
    const int warp_m = wid >> 2, warp_n = wid & 3;
    const int m0 = blockIdx.x * 64;

    const __half* __restrict__ B = (LAYER == 1) ? g_B1 : g_B2;

    // ldmatrix lane offsets
    const uint32_t aLaneOff = (lane & 15) * PITCH + (lane >> 4) * 16;
    const uint32_t n16 = (lane & 7) + ((lane >> 4) << 3);
    const uint32_t bLaneOff = n16 * PITCH + ((lane >> 3) & 1) * 16;

    // cp.async assignments: A 1 chunk/thread, B 2 chunks/thread (16B each)
    const int arow = tid >> 2, ac16 = tid & 3;
    const __half* gA = g_Ah + (size_t)(m0 + arow) * NN + ac16 * 8;
    const uint32_t sAoff = AH_OFF + arow * PITCH + ac16 * 16;
    const int brow0 = tid >> 2, brow1 = brow0 + 64;      // same c16
    const __half* gB0 = B + (size_t)brow0 * NN + ac16 * 8;
    const __half* gB1 = B + (size_t)brow1 * NN + ac16 * 8;
    const uint32_t sBoff0 = BH_OFF + brow0 * PITCH + ac16 * 16;
    const uint32_t sBoff1 = BH_OFF + brow1 * PITCH + ac16 * 16;

    float am[2][4][4];
    #pragma unroll
    for (int i = 0; i < 2; ++i)
        #pragma unroll
        for (int j = 0; j < 4; ++j)
            #pragma unroll
            for (int q = 0; q < 4; ++q) am[i][j][q] = 0.0f;

    // ---- prologue: issue stages 0..2 ----
    #pragma unroll
    for (int s = 0; s < NSTAGE - 1; ++s) {
        const uint32_t bb = sb + (uint32_t)s * BUF_BYTES;
        const int kc = s * 32;
        cp16(bb + sAoff,  gA  + kc);
        cp16(bb + sBoff0, gB0 + kc);
        cp16(bb + sBoff1, gB1 + kc);
        CP_COMMIT();
    }

    // ---- main loop: 256 chunks of BK=32 ----
    #pragma unroll 1
    for (int t = 0; t < 256; ++t) {
        CP_WAIT2();            // stage t landed (per-thread)
        __syncthreads();       // visible to all; all done reading buf (t-1)%4

        const int tp = t + NSTAGE - 1;
        if (tp < 256) {        // issue stage t+3 into buf (t+3)%4
            const uint32_t bb = sb + (uint32_t)(tp & (NSTAGE - 1)) * BUF_BYTES;
            const int kc = tp * 32;
            cp16(bb + sAoff,  gA  + kc);
            cp16(bb + sBoff0, gB0 + kc);
            cp16(bb + sBoff1, gB1 + kc);
        }
        CP_COMMIT();           // commit every iter (possibly empty group)

        compute_tile(sb + (uint32_t)(t & (NSTAGE - 1)) * BUF_BYTES,
                     aLaneOff, bLaneOff, warp_m, warp_n, am);
    }
    __syncthreads();

    // ---- epilogue: v = main / 8192, relu cols<64 ----
    const int r_base = warp_m * 32 + (lane >> 2);
    const int c_base = warp_n * 32 + (lane & 3) * 2;
    constexpr float INV_SC = 1.0f / 8192.0f;

    if (LAYER == 1) {
        // stage fp32 [n][k] in smem (pitch 68 floats), then coalesced f16 out
        float* sE = reinterpret_cast<float*>(smem);
        #pragma unroll
        for (int mt = 0; mt < 2; ++mt)
            #pragma unroll
            for (int nt = 0; nt < 4; ++nt) {
                int r = r_base + mt * 16;
                int c = c_base + nt * 8;
                float v[4];
                #pragma unroll
                for (int q = 0; q < 4; ++q) v[q] = am[mt][nt][q] * INV_SC;
                if (c < 64) {
                    #pragma unroll
                    for (int q = 0; q < 4; ++q) v[q] = fmaxf(v[q], 0.0f);
                }
                sE[(c    ) * 68 + r    ] = v[0];
                sE[(c + 1) * 68 + r    ] = v[1];
                sE[(c    ) * 68 + r + 8] = v[2];
                sE[(c + 1) * 68 + r + 8] = v[3];
            }
        __syncthreads();
        const int n = tid >> 1, k0 = (tid & 1) * 32;
        const float* src = sE + n * 68 + k0;
        uint32_t w[16];
        #pragma unroll
        for (int j = 0; j < 16; ++j)
            w[j] = packh(__float2half_rn(src[2 * j]),
                         __float2half_rn(src[2 * j + 1]));
        uint4* dst = reinterpret_cast<uint4*>(g_B2 + (size_t)n * NN + m0 + k0);
        #pragma unroll
        for (int q = 0; q < 4; ++q)
            dst[q] = make_uint4(w[4 * q], w[4 * q + 1], w[4 * q + 2], w[4 * q + 3]);
    } else {
        #pragma unroll
        for (int mt = 0; mt < 2; ++mt)
            #pragma unroll
            for (int nt = 0; nt < 4; ++nt) {
                int r = m0 + r_base + mt * 16;
                int c = c_base + nt * 8;
                float v[4];
                #pragma unroll
                for (int q = 0; q < 4; ++q) v[q] = am[mt][nt][q] * INV_SC;
                if (c < 64) {
                    #pragma unroll
                    for (int q = 0; q < 4; ++q) v[q] = fmaxf(v[q], 0.0f);
                }
                *reinterpret_cast<float2*>(&outp[(size_t)r * WID + c]) =
                    make_float2(v[0], v[1]);
                *reinterpret_cast<float2*>(&outp[(size_t)(r + 8) * WID + c]) =
                    make_float2(v[2], v[3]);
            }
    }
}

// ---------------------------------------------------------------------------
// launch: conv_a + conv_b1 -> layer1 -> layer2. Graph-capturable,
// allocation-free, deterministic.
// ---------------------------------------------------------------------------
extern "C" void kernel_launch(void* const* d_in, const int* in_sizes, int n_in,
                              void* d_out, int out_size) {
    const float* A  = (const float*)d_in[0];
    const float* F  = (const float*)d_in[1];
    const float* NF = (const float*)d_in[2];
    float* out = (float*)d_out;

    cudaFuncSetAttribute(gemm_f16<1>, cudaFuncAttributeMaxDynamicSharedMemorySize, SMEM_GEMM);
    cudaFuncSetAttribute(gemm_f16<2>, cudaFuncAttributeMaxDynamicSharedMemorySize, SMEM_GEMM);

    conv_a<<<(int)((size_t)NN * NN / 8 / 256), 256>>>(A);
    conv_b1<<<dim3(NN / 32, WID / 32), dim3(32, 8)>>>(F, NF);
    gemm_f16<1><<<NN / 64, 256, SMEM_GEMM>>>(nullptr);
    gemm_f16<2><<<NN / 64, 256, SMEM_GEMM>>>(out);
}